// round 1
// baseline (speedup 1.0000x reference)
#include <cuda_runtime.h>
#include <cuda_bf16.h>
#include <cstdint>

// CIF: continuous integrate-and-fire.
// B=32, T=2000, H=512, L=256, THRESHOLD=0.95
//
// Phase A (scan): per batch row, compute scale = target/sum(alphas) (double-
// precision sum, fp32 round), then sequentially replicate the reference fp32
// recurrence to get per-frame weights p[t], fire positions fpos[k], and the
// carry weights rem[k].
// Phase B (gather): out[b,k,:] = rem[k-1]*h[fpos[k-1]] + sum p[t]*h[t] over
// the token's contiguous segment. Zero rows for k >= n_fires.

#define CIF_B 32
#define CIF_T 2000
#define CIF_H 512
#define CIF_L 256
#define CIF_THRESH 0.95f

// Scratch (allocation-free contract: __device__ globals)
__device__ float g_p[CIF_B * CIF_T];     // per-frame primary weight (cur)
__device__ int   g_fpos[CIF_B * CIF_L];  // fire position of token k
__device__ float g_rem[CIF_B * CIF_L];   // carry weight seeding token k+1
__device__ int   g_nf[CIF_B];            // number of fires (uncapped)

// ---------------------------------------------------------------------------
// Kernel A: per-row rescale + sequential integrate-and-fire scan
// one CTA per batch row, 256 threads
// ---------------------------------------------------------------------------
__global__ __launch_bounds__(256, 1)
void cif_scan_kernel(const float* __restrict__ alphas,
                     const int* __restrict__ target_lengths)
{
    __shared__ float  s_a[CIF_T];
    __shared__ double s_red[256];
    __shared__ float  s_scale;

    const int b   = blockIdx.x;
    const int tid = threadIdx.x;
    const float* arow = alphas + b * CIF_T;

    // --- double-precision deterministic row sum ---
    double acc = 0.0;
    for (int t = tid; t < CIF_T; t += 256)
        acc += (double)arow[t];
    s_red[tid] = acc;
    __syncthreads();
    for (int off = 128; off > 0; off >>= 1) {
        if (tid < off) s_red[tid] += s_red[tid + off];
        __syncthreads();
    }
    if (tid == 0) {
        float fsum = (float)s_red[0];
        float num  = (float)target_lengths[b];
        s_scale = num / fsum;                    // fp32 divide, like reference
    }
    __syncthreads();

    // --- scaled alphas into smem (fp32 elementwise mul, like reference) ---
    const float scale = s_scale;
    for (int t = tid; t < CIF_T; t += 256)
        s_a[t] = arow[t] * scale;
    __syncthreads();

    // --- sequential scan (thread 0 only; replicates reference op order) ---
    if (tid == 0) {
        float integ = 0.0f;
        int nf = 0;
        int* fp = g_fpos + b * CIF_L;
        float* rm = g_rem + b * CIF_L;
        for (int t = 0; t < CIF_T; ++t) {
            float a  = s_a[t];
            float i2 = integ + a;                 // integrate += alpha
            if (i2 >= CIF_THRESH) {               // fire
                float cur = 1.0f - integ;         // dist_completion
                s_a[t] = cur;                     // p[t] = cur
                if (nf < CIF_L) {
                    fp[nf] = t;
                    rm[nf] = a - cur;             // remainds
                }
                nf++;
                integ = i2 - 1.0f;
            } else {
                // p[t] = a (already in s_a[t])
                integ = i2;
            }
        }
        g_nf[b] = nf;
    }
    __syncthreads();

    // --- flush weights to global ---
    float* prow = g_p + b * CIF_T;
    for (int t = tid; t < CIF_T; t += 256)
        prow[t] = s_a[t];
}

// ---------------------------------------------------------------------------
// Kernel B: segmented weighted gather
// grid (L, B), 128 threads; each thread owns one float4 of H=512
// ---------------------------------------------------------------------------
__global__ __launch_bounds__(128, 8)
void cif_gather_kernel(const float* __restrict__ hidden,
                       float* __restrict__ out)
{
    const int k = blockIdx.x;
    const int b = blockIdx.y;
    const int tid = threadIdx.x;

    float4* out4 = reinterpret_cast<float4*>(out + ((size_t)(b * CIF_L + k)) * CIF_H) + tid;

    int nf = g_nf[b];
    nf = nf < CIF_L ? nf : CIF_L;
    if (k >= nf) {
        *out4 = make_float4(0.f, 0.f, 0.f, 0.f);
        return;
    }

    const int te = g_fpos[b * CIF_L + k];
    const float4* h4 = reinterpret_cast<const float4*>(hidden + (size_t)b * CIF_T * CIF_H) + tid;
    const float* prow = g_p + b * CIF_T;

    float4 accv;
    int t0;
    if (k == 0) {
        t0 = 0;
        accv = make_float4(0.f, 0.f, 0.f, 0.f);
    } else {
        const int ts = g_fpos[b * CIF_L + k - 1];
        const float w = g_rem[b * CIF_L + k - 1];
        float4 hv = __ldg(h4 + (size_t)ts * (CIF_H / 4));
        accv = make_float4(w * hv.x, w * hv.y, w * hv.z, w * hv.w);
        t0 = ts + 1;
    }

    for (int t = t0; t <= te; ++t) {
        float w = __ldg(prow + t);
        float4 hv = __ldg(h4 + (size_t)t * (CIF_H / 4));
        accv.x = fmaf(w, hv.x, accv.x);
        accv.y = fmaf(w, hv.y, accv.y);
        accv.z = fmaf(w, hv.z, accv.z);
        accv.w = fmaf(w, hv.w, accv.w);
    }
    *out4 = accv;
}

// ---------------------------------------------------------------------------
extern "C" void kernel_launch(void* const* d_in, const int* in_sizes, int n_in,
                              void* d_out, int out_size)
{
    const float* hidden = (const float*)d_in[0];
    const float* alphas = (const float*)d_in[1];
    const int*   tlen   = (const int*)d_in[2];
    float* out = (float*)d_out;

    cif_scan_kernel<<<CIF_B, 256>>>(alphas, tlen);
    dim3 grid(CIF_L, CIF_B);
    cif_gather_kernel<<<grid, 128>>>(hidden, out);
}

// round 2
// speedup vs baseline: 1.2353x; 1.2353x over previous
#include <cuda_runtime.h>
#include <cuda_bf16.h>
#include <cstdint>

// CIF: continuous integrate-and-fire. B=32, T=2000, H=512, L=256, thresh=0.95
//
// Phase A (scan): per batch row: double-precision row sum -> scale; then a
// branchless sequential fp32 recurrence (bit-identical op order to the JAX
// reference) producing per-frame weights p[t], fire positions, carry weights.
// Critical chain per step: FADD -> FSETP -> FSEL (pred-as-data) ~ 12 cyc.
// Phase B (gather): out[b,k,:] = rem[k-1]*h[f_{k-1}] + sum p[t]*h[t] over the
// token's contiguous frame segment; manual unroll-4 for MLP.

#define CIF_B 32
#define CIF_T 2000
#define CIF_H 512
#define CIF_L 256
#define CIF_THRESH 0.95f

// Scratch (allocation-free contract: __device__ globals)
__device__ float g_p[CIF_B * CIF_T];     // per-frame weight (cur at fires, a otherwise)
__device__ int   g_fpos[CIF_B * CIF_L];  // fire position of token k
__device__ float g_rem[CIF_B * CIF_L];   // carry weight seeding token k+1
__device__ int   g_nf[CIF_B];            // number of fires (uncapped)

// ---------------------------------------------------------------------------
// Kernel A: rescale + branchless sequential integrate-and-fire scan
// one CTA per batch row, 256 threads
// ---------------------------------------------------------------------------
__global__ __launch_bounds__(256, 1)
void cif_scan_kernel(const float* __restrict__ alphas,
                     const int* __restrict__ target_lengths)
{
    __shared__ float  s_a[CIF_T];     // scaled alphas (read-only in scan)
    __shared__ float  s_p[CIF_T];     // per-frame weights (written in scan)
    __shared__ int    s_fp[CIF_L];
    __shared__ float  s_rm[CIF_L];
    __shared__ double s_red[256];
    __shared__ float  s_scale;
    __shared__ int    s_nf;

    const int b   = blockIdx.x;
    const int tid = threadIdx.x;
    const float* arow = alphas + b * CIF_T;

    // --- deterministic double-precision row sum ---
    double acc = 0.0;
    for (int t = tid; t < CIF_T; t += 256)
        acc += (double)arow[t];
    s_red[tid] = acc;
    __syncthreads();
    for (int off = 128; off > 0; off >>= 1) {
        if (tid < off) s_red[tid] += s_red[tid + off];
        __syncthreads();
    }
    if (tid == 0) {
        float fsum = (float)s_red[0];
        s_scale = (float)target_lengths[b] / fsum;   // fp32 divide like reference
    }
    __syncthreads();

    // --- scaled alphas into smem (fp32 mul, like reference) ---
    const float scale = s_scale;
    for (int t = tid; t < CIF_T; t += 256)
        s_a[t] = arow[t] * scale;
    __syncthreads();

    // --- branchless sequential scan on thread 0 ---
    if (tid == 0) {
        float integ = 0.0f;
        int nf = 0;
        #pragma unroll 4
        for (int t = 0; t < CIF_T; ++t) {
            float a    = s_a[t];
            float i2   = integ + a;               // fl(integ + alpha)
            bool  fire = (i2 >= CIF_THRESH);
            float cur  = 1.0f - integ;            // dist_completion (old integ)
            float d    = i2 - 1.0f;               // exact (Sterbenz: i2 in [0.95,1.3))
            float pt   = fire ? cur : a;
            float rm   = a - cur;                 // remainds (only meaningful at fires)
            int   idx  = nf < (CIF_L - 1) ? nf : (CIF_L - 1);
            s_p[t]     = pt;
            s_fp[idx]  = t;                       // overwritten until nf advances
            s_rm[idx]  = rm;
            integ      = fire ? d : i2;           // FSEL, pred-as-data
            nf        += fire ? 1 : 0;
        }
        s_nf = nf;
    }
    __syncthreads();

    // --- parallel flush to global ---
    float* prow = g_p + b * CIF_T;
    for (int t = tid; t < CIF_T; t += 256)
        prow[t] = s_p[t];
    if (tid < CIF_L) {
        g_fpos[b * CIF_L + tid] = s_fp[tid];
        g_rem [b * CIF_L + tid] = s_rm[tid];
    }
    if (tid == 0)
        g_nf[b] = s_nf;
}

// ---------------------------------------------------------------------------
// Kernel B: segmented weighted gather, unroll-4 for MLP
// grid (L, B), 128 threads; each thread owns one float4 of H=512
// ---------------------------------------------------------------------------
__global__ __launch_bounds__(128, 12)
void cif_gather_kernel(const float* __restrict__ hidden,
                       float* __restrict__ out)
{
    const int k   = blockIdx.x;
    const int b   = blockIdx.y;
    const int tid = threadIdx.x;

    float4* out4 = reinterpret_cast<float4*>(out + ((size_t)(b * CIF_L + k)) * CIF_H) + tid;

    int nf = g_nf[b];
    nf = nf < CIF_L ? nf : CIF_L;
    if (k >= nf) {
        *out4 = make_float4(0.f, 0.f, 0.f, 0.f);
        return;
    }

    const int    te   = g_fpos[b * CIF_L + k];
    const float4* h4  = reinterpret_cast<const float4*>(hidden + (size_t)b * CIF_T * CIF_H) + tid;
    const float* prow = g_p + b * CIF_T;
    const int    HS   = CIF_H / 4;   // float4 row stride

    float4 accv;
    int t0;
    if (k == 0) {
        t0 = 0;
        accv = make_float4(0.f, 0.f, 0.f, 0.f);
    } else {
        const int   ts = g_fpos[b * CIF_L + k - 1];
        const float w  = g_rem[b * CIF_L + k - 1];
        float4 hv = __ldg(h4 + (size_t)ts * HS);
        accv = make_float4(w * hv.x, w * hv.y, w * hv.z, w * hv.w);
        t0 = ts + 1;
    }

    int t = t0;
    // main loop: 4 iterations in flight (loads batched ahead of FMAs)
    for (; t + 3 <= te; t += 4) {
        float w0 = __ldg(prow + t);
        float w1 = __ldg(prow + t + 1);
        float w2 = __ldg(prow + t + 2);
        float w3 = __ldg(prow + t + 3);
        float4 h0 = __ldg(h4 + (size_t)(t    ) * HS);
        float4 h1 = __ldg(h4 + (size_t)(t + 1) * HS);
        float4 h2 = __ldg(h4 + (size_t)(t + 2) * HS);
        float4 h3 = __ldg(h4 + (size_t)(t + 3) * HS);
        accv.x = fmaf(w0, h0.x, accv.x); accv.y = fmaf(w0, h0.y, accv.y);
        accv.z = fmaf(w0, h0.z, accv.z); accv.w = fmaf(w0, h0.w, accv.w);
        accv.x = fmaf(w1, h1.x, accv.x); accv.y = fmaf(w1, h1.y, accv.y);
        accv.z = fmaf(w1, h1.z, accv.z); accv.w = fmaf(w1, h1.w, accv.w);
        accv.x = fmaf(w2, h2.x, accv.x); accv.y = fmaf(w2, h2.y, accv.y);
        accv.z = fmaf(w2, h2.z, accv.z); accv.w = fmaf(w2, h2.w, accv.w);
        accv.x = fmaf(w3, h3.x, accv.x); accv.y = fmaf(w3, h3.y, accv.y);
        accv.z = fmaf(w3, h3.z, accv.z); accv.w = fmaf(w3, h3.w, accv.w);
    }
    for (; t <= te; ++t) {
        float  w  = __ldg(prow + t);
        float4 hv = __ldg(h4 + (size_t)t * HS);
        accv.x = fmaf(w, hv.x, accv.x);
        accv.y = fmaf(w, hv.y, accv.y);
        accv.z = fmaf(w, hv.z, accv.z);
        accv.w = fmaf(w, hv.w, accv.w);
    }
    *out4 = accv;
}

// ---------------------------------------------------------------------------
extern "C" void kernel_launch(void* const* d_in, const int* in_sizes, int n_in,
                              void* d_out, int out_size)
{
    const float* hidden = (const float*)d_in[0];
    const float* alphas = (const float*)d_in[1];
    const int*   tlen   = (const int*)d_in[2];
    float* out = (float*)d_out;

    cif_scan_kernel<<<CIF_B, 256>>>(alphas, tlen);
    dim3 grid(CIF_L, CIF_B);
    cif_gather_kernel<<<grid, 128>>>(hidden, out);
}

// round 3
// speedup vs baseline: 1.6049x; 1.2992x over previous
#include <cuda_runtime.h>
#include <cuda_bf16.h>
#include <cstdint>

// CIF: continuous integrate-and-fire. B=32, T=2000, H=512, L=256, thresh=0.95
//
// Phase A (scan), per batch row:
//   1. double-precision row sum -> fp32 scale (matches reference closely)
//   2. MINIMAL serial fp32 chain on thread 0 (only integ + fire count), with
//      (integ, nf) checkpoints every 32 steps. Chain: FADD->FSETP->FSEL = 12cyc.
//   3. 63 threads replay their 32-step chunk from the checkpoint with the
//      IDENTICAL op order (bit-exact) and emit p[t], fpos[k], rem[k].
// Phase B (gather): persistent CTAs stride over (b,k) work items;
//   out[b,k,:] = rem[k-1]*h[f_{k-1}] + sum p[t]*h[t] over the token segment.

#define CIF_B 32
#define CIF_T 2000
#define CIF_H 512
#define CIF_L 256
#define CIF_THRESH 0.95f

#define CHUNK 32
#define NCHUNK 63                 // 63*32 = 2016 >= 2000 (padded with zeros)
#define T_PAD (NCHUNK * CHUNK)

#define GATHER_CTAS 1776          // 148 SMs * 12
#define GATHER_THREADS 128

// Scratch (allocation-free contract: __device__ globals)
__device__ float g_p[CIF_B * CIF_T];     // per-frame weight
__device__ int   g_fpos[CIF_B * CIF_L];  // fire position of token k
__device__ float g_rem[CIF_B * CIF_L];   // carry weight seeding token k+1
__device__ int   g_nf[CIF_B];            // number of fires (<= 256)

// ---------------------------------------------------------------------------
// Kernel A: rescale + minimal serial scan + parallel bit-exact reconstruction
// one CTA per batch row, 256 threads
// ---------------------------------------------------------------------------
__global__ __launch_bounds__(256, 1)
void cif_scan_kernel(const float* __restrict__ alphas,
                     const int* __restrict__ target_lengths)
{
    __shared__ float  s_a[T_PAD];      // scaled alphas, zero-padded
    __shared__ float  s_p[CIF_T];      // per-frame weights
    __shared__ int    s_fp[CIF_L];
    __shared__ float  s_rm[CIF_L];
    __shared__ float  s_i0[NCHUNK];    // chunk-start integ
    __shared__ int    s_n0[NCHUNK + 1];// chunk-start fire count (+ final)
    __shared__ double s_red[256];
    __shared__ float  s_scale;

    const int b   = blockIdx.x;
    const int tid = threadIdx.x;
    const float* arow = alphas + b * CIF_T;

    // --- deterministic double-precision row sum ---
    double acc = 0.0;
    for (int t = tid; t < CIF_T; t += 256)
        acc += (double)arow[t];
    s_red[tid] = acc;
    __syncthreads();
    for (int off = 128; off > 0; off >>= 1) {
        if (tid < off) s_red[tid] += s_red[tid + off];
        __syncthreads();
    }
    if (tid == 0)
        s_scale = (float)target_lengths[b] / (float)s_red[0];
    __syncthreads();

    // --- scaled alphas into smem (fp32 mul, like reference); pad with zeros ---
    const float scale = s_scale;
    for (int t = tid; t < T_PAD; t += 256)
        s_a[t] = (t < CIF_T) ? arow[t] * scale : 0.0f;
    __syncthreads();

    // --- minimal serial chain on thread 0: only integ + fire count ---
    if (tid == 0) {
        float integ = 0.0f;
        int nf = 0;
        #pragma unroll 1
        for (int c = 0; c < NCHUNK; ++c) {
            s_i0[c] = integ;
            s_n0[c] = nf;
            const float* ac = s_a + c * CHUNK;
            #pragma unroll
            for (int j = 0; j < CHUNK; ++j) {
                float a    = ac[j];
                float i2   = integ + a;               // fl(integ + alpha)
                bool  fire = (i2 >= CIF_THRESH);
                integ      = fire ? (i2 - 1.0f) : i2; // Sterbenz-exact subtract
                nf        += fire ? 1 : 0;
            }
        }
        s_n0[NCHUNK] = nf;
        g_nf[b] = nf;
    }
    __syncthreads();

    // --- parallel reconstruction: thread c replays chunk c, bit-identically ---
    if (tid < NCHUNK) {
        float integ = s_i0[tid];
        int   nf    = s_n0[tid];
        const int tbase = tid * CHUNK;
        #pragma unroll
        for (int j = 0; j < CHUNK; ++j) {
            int   t    = tbase + j;
            float a    = s_a[t];
            float i2   = integ + a;
            bool  fire = (i2 >= CIF_THRESH);
            float cur  = 1.0f - integ;            // dist_completion (old integ)
            if (t < CIF_T) {
                s_p[t] = fire ? cur : a;
                if (fire) {
                    if (nf < CIF_L) {
                        s_fp[nf] = t;
                        s_rm[nf] = a - cur;       // remainds
                    }
                    nf++;
                }
            }
            integ = fire ? (i2 - 1.0f) : i2;
        }
    }
    __syncthreads();

    // --- flush to global ---
    float* prow = g_p + b * CIF_T;
    for (int t = tid; t < CIF_T; t += 256)
        prow[t] = s_p[t];
    int nf_tot = s_n0[NCHUNK];
    if (tid < CIF_L && tid < nf_tot) {
        g_fpos[b * CIF_L + tid] = s_fp[tid];
        g_rem [b * CIF_L + tid] = s_rm[tid];
    }
}

// ---------------------------------------------------------------------------
// Kernel B: persistent segmented weighted gather
// 1776 CTAs x 128 threads; CTA strides over (b,k) work items
// ---------------------------------------------------------------------------
__global__ __launch_bounds__(GATHER_THREADS, 12)
void cif_gather_kernel(const float* __restrict__ hidden,
                       float* __restrict__ out)
{
    const int tid = threadIdx.x;
    const int HS  = CIF_H / 4;   // float4 row stride

    for (int w = blockIdx.x; w < CIF_B * CIF_L; w += GATHER_CTAS) {
        const int b = w >> 8;          // w / 256
        const int k = w & 255;         // w % 256

        float4* out4 = reinterpret_cast<float4*>(out + (size_t)w * CIF_H) + tid;

        int nf = g_nf[b];
        nf = nf < CIF_L ? nf : CIF_L;
        if (k >= nf) {
            *out4 = make_float4(0.f, 0.f, 0.f, 0.f);
            continue;
        }

        const int     te   = g_fpos[b * CIF_L + k];
        const float4* h4   = reinterpret_cast<const float4*>(hidden + (size_t)b * CIF_T * CIF_H) + tid;
        const float*  prow = g_p + b * CIF_T;

        float4 accv;
        int t0;
        if (k == 0) {
            t0 = 0;
            accv = make_float4(0.f, 0.f, 0.f, 0.f);
        } else {
            const int   ts = g_fpos[b * CIF_L + k - 1];
            const float wt = g_rem[b * CIF_L + k - 1];
            float4 hv = __ldg(h4 + (size_t)ts * HS);
            accv = make_float4(wt * hv.x, wt * hv.y, wt * hv.z, wt * hv.w);
            t0 = ts + 1;
        }

        int t = t0;
        for (; t + 3 <= te; t += 4) {
            float w0 = __ldg(prow + t);
            float w1 = __ldg(prow + t + 1);
            float w2 = __ldg(prow + t + 2);
            float w3 = __ldg(prow + t + 3);
            float4 h0 = __ldg(h4 + (size_t)(t    ) * HS);
            float4 h1 = __ldg(h4 + (size_t)(t + 1) * HS);
            float4 h2 = __ldg(h4 + (size_t)(t + 2) * HS);
            float4 h3 = __ldg(h4 + (size_t)(t + 3) * HS);
            accv.x = fmaf(w0, h0.x, accv.x); accv.y = fmaf(w0, h0.y, accv.y);
            accv.z = fmaf(w0, h0.z, accv.z); accv.w = fmaf(w0, h0.w, accv.w);
            accv.x = fmaf(w1, h1.x, accv.x); accv.y = fmaf(w1, h1.y, accv.y);
            accv.z = fmaf(w1, h1.z, accv.z); accv.w = fmaf(w1, h1.w, accv.w);
            accv.x = fmaf(w2, h2.x, accv.x); accv.y = fmaf(w2, h2.y, accv.y);
            accv.z = fmaf(w2, h2.z, accv.z); accv.w = fmaf(w2, h2.w, accv.w);
            accv.x = fmaf(w3, h3.x, accv.x); accv.y = fmaf(w3, h3.y, accv.y);
            accv.z = fmaf(w3, h3.z, accv.z); accv.w = fmaf(w3, h3.w, accv.w);
        }
        for (; t <= te; ++t) {
            float  wt = __ldg(prow + t);
            float4 hv = __ldg(h4 + (size_t)t * HS);
            accv.x = fmaf(wt, hv.x, accv.x);
            accv.y = fmaf(wt, hv.y, accv.y);
            accv.z = fmaf(wt, hv.z, accv.z);
            accv.w = fmaf(wt, hv.w, accv.w);
        }
        *out4 = accv;
    }
}

// ---------------------------------------------------------------------------
extern "C" void kernel_launch(void* const* d_in, const int* in_sizes, int n_in,
                              void* d_out, int out_size)
{
    const float* hidden = (const float*)d_in[0];
    const float* alphas = (const float*)d_in[1];
    const int*   tlen   = (const int*)d_in[2];
    float* out = (float*)d_out;

    cif_scan_kernel<<<CIF_B, 256>>>(alphas, tlen);
    cif_gather_kernel<<<GATHER_CTAS, GATHER_THREADS>>>(hidden, out);
}

// round 4
// speedup vs baseline: 1.7030x; 1.0612x over previous
#include <cuda_runtime.h>
#include <cuda_bf16.h>
#include <cstdint>

// CIF: continuous integrate-and-fire. B=32, T=2000, H=512, L=256, thresh=0.95
//
// Phase A (scan), one CTA per batch row:
//   1. double-precision row sum -> fp32 scale
//   2. minimal serial fp32 chain on thread 0 (inline PTX: add/setp/selp so the
//      select is FSEL pred-as-data, 12-cyc chain), checkpoints every 32 steps
//   3. 63 threads replay their chunk bit-identically, emit p[t], fpos, rem
// Phase B (gather): grid (L,B) x 128 threads;
//   out[b,k,:] = rem[k-1]*h[f_{k-1}] + sum p[t]*h[t] over the token segment.

#define CIF_B 32
#define CIF_T 2000
#define CIF_H 512
#define CIF_L 256
#define CIF_THRESH 0.95f

#define CHUNK 32
#define NCHUNK 63                 // 63*32 = 2016 >= 2000 (zero-padded)
#define T_PAD (NCHUNK * CHUNK)

// Scratch (allocation-free contract: __device__ globals)
__device__ float g_p[CIF_B * CIF_T];     // per-frame weight
__device__ int   g_fpos[CIF_B * CIF_L];  // fire position of token k
__device__ float g_rem[CIF_B * CIF_L];   // carry weight seeding token k+1
__device__ int   g_nf[CIF_B];            // number of fires

// one CIF step, chain forced to add->setp->selp (12 cyc), fire count off-chain
__device__ __forceinline__ void cif_step_asm(float a, float& integ, int& nf)
{
    float i2, sub;
    int f;
    asm("{\n\t"
        ".reg .pred p;\n\t"
        "add.f32 %0, %2, %4;\n\t"               // i2 = integ + a
        "setp.ge.f32 p, %0, 0f3F733333;\n\t"    // p = (i2 >= 0.95f)
        "add.f32 %1, %0, 0fBF800000;\n\t"       // sub = i2 - 1.0f (off-chain)
        "selp.f32 %2, %1, %0, p;\n\t"           // integ = p ? sub : i2
        "selp.s32 %3, 1, 0, p;\n\t"             // f = p ? 1 : 0 (off-chain)
        "}"
        : "=f"(i2), "=f"(sub), "+f"(integ), "=r"(f)
        : "f"(a));
    nf += f;
}

// ---------------------------------------------------------------------------
// Kernel A: rescale + minimal serial scan + parallel bit-exact reconstruction
// ---------------------------------------------------------------------------
__global__ __launch_bounds__(256, 1)
void cif_scan_kernel(const float* __restrict__ alphas,
                     const int* __restrict__ target_lengths)
{
    __shared__ float  s_a[T_PAD];      // scaled alphas, zero-padded
    __shared__ float  s_p[CIF_T];      // per-frame weights
    __shared__ int    s_fp[CIF_L];
    __shared__ float  s_rm[CIF_L];
    __shared__ float  s_i0[NCHUNK];    // chunk-start integ
    __shared__ int    s_n0[NCHUNK + 1];// chunk-start fire count (+ final)
    __shared__ double s_red[256];
    __shared__ float  s_scale;

    const int b   = blockIdx.x;
    const int tid = threadIdx.x;
    const float* arow = alphas + b * CIF_T;

    // --- deterministic double-precision row sum ---
    double acc = 0.0;
    for (int t = tid; t < CIF_T; t += 256)
        acc += (double)arow[t];
    s_red[tid] = acc;
    __syncthreads();
    for (int off = 128; off > 0; off >>= 1) {
        if (tid < off) s_red[tid] += s_red[tid + off];
        __syncthreads();
    }
    if (tid == 0)
        s_scale = (float)target_lengths[b] / (float)s_red[0];
    __syncthreads();

    // --- scaled alphas into smem (fp32 mul, like reference); zero pad ---
    const float scale = s_scale;
    for (int t = tid; t < T_PAD; t += 256)
        s_a[t] = (t < CIF_T) ? arow[t] * scale : 0.0f;
    __syncthreads();

    // --- minimal serial chain on thread 0: only integ + fire count ---
    if (tid == 0) {
        float integ = 0.0f;
        int nf = 0;
        #pragma unroll 1
        for (int c = 0; c < NCHUNK; ++c) {
            s_i0[c] = integ;
            s_n0[c] = nf;
            const float* ac = s_a + c * CHUNK;
            #pragma unroll
            for (int j = 0; j < CHUNK; ++j)
                cif_step_asm(ac[j], integ, nf);
        }
        s_n0[NCHUNK] = nf;
        g_nf[b] = nf;
    }
    __syncthreads();

    // --- parallel reconstruction: thread c replays chunk c, bit-identically ---
    if (tid < NCHUNK) {
        float integ = s_i0[tid];
        int   nf    = s_n0[tid];
        const int tbase = tid * CHUNK;
        #pragma unroll
        for (int j = 0; j < CHUNK; ++j) {
            int   t    = tbase + j;
            float a    = s_a[t];
            float i2   = integ + a;               // same add
            bool  fire = (i2 >= CIF_THRESH);      // same compare
            float cur  = 1.0f - integ;            // dist_completion (old integ)
            if (t < CIF_T) {
                s_p[t] = fire ? cur : a;
                if (fire) {
                    if (nf < CIF_L) {
                        s_fp[nf] = t;
                        s_rm[nf] = a - cur;       // remainds
                    }
                    nf++;
                }
            }
            integ = fire ? (i2 - 1.0f) : i2;      // same Sterbenz-exact subtract
        }
    }
    __syncthreads();

    // --- flush to global ---
    float* prow = g_p + b * CIF_T;
    for (int t = tid; t < CIF_T; t += 256)
        prow[t] = s_p[t];
    int nf_tot = s_n0[NCHUNK];
    if (tid < CIF_L && tid < nf_tot) {
        g_fpos[b * CIF_L + tid] = s_fp[tid];
        g_rem [b * CIF_L + tid] = s_rm[tid];
    }
}

// ---------------------------------------------------------------------------
// Kernel B: segmented weighted gather (grid (L,B), 128 threads; one float4/thread)
// ---------------------------------------------------------------------------
__global__ __launch_bounds__(128, 12)
void cif_gather_kernel(const float* __restrict__ hidden,
                       float* __restrict__ out)
{
    const int k   = blockIdx.x;
    const int b   = blockIdx.y;
    const int tid = threadIdx.x;
    const int HS  = CIF_H / 4;   // float4 row stride

    float4* out4 = reinterpret_cast<float4*>(out + ((size_t)(b * CIF_L + k)) * CIF_H) + tid;

    int nf = g_nf[b];
    nf = nf < CIF_L ? nf : CIF_L;
    if (k >= nf) {
        *out4 = make_float4(0.f, 0.f, 0.f, 0.f);
        return;
    }

    const int     te   = g_fpos[b * CIF_L + k];
    const float4* h4   = reinterpret_cast<const float4*>(hidden + (size_t)b * CIF_T * CIF_H) + tid;
    const float*  prow = g_p + b * CIF_T;

    float4 accv;
    int t0;
    if (k == 0) {
        t0 = 0;
        accv = make_float4(0.f, 0.f, 0.f, 0.f);
    } else {
        const int   ts = g_fpos[b * CIF_L + k - 1];
        const float wt = g_rem[b * CIF_L + k - 1];
        float4 hv = __ldg(h4 + (size_t)ts * HS);
        accv = make_float4(wt * hv.x, wt * hv.y, wt * hv.z, wt * hv.w);
        t0 = ts + 1;
    }

    int t = t0;
    for (; t + 3 <= te; t += 4) {
        float w0 = __ldg(prow + t);
        float w1 = __ldg(prow + t + 1);
        float w2 = __ldg(prow + t + 2);
        float w3 = __ldg(prow + t + 3);
        float4 h0 = __ldg(h4 + (size_t)(t    ) * HS);
        float4 h1 = __ldg(h4 + (size_t)(t + 1) * HS);
        float4 h2 = __ldg(h4 + (size_t)(t + 2) * HS);
        float4 h3 = __ldg(h4 + (size_t)(t + 3) * HS);
        accv.x = fmaf(w0, h0.x, accv.x); accv.y = fmaf(w0, h0.y, accv.y);
        accv.z = fmaf(w0, h0.z, accv.z); accv.w = fmaf(w0, h0.w, accv.w);
        accv.x = fmaf(w1, h1.x, accv.x); accv.y = fmaf(w1, h1.y, accv.y);
        accv.z = fmaf(w1, h1.z, accv.z); accv.w = fmaf(w1, h1.w, accv.w);
        accv.x = fmaf(w2, h2.x, accv.x); accv.y = fmaf(w2, h2.y, accv.y);
        accv.z = fmaf(w2, h2.z, accv.z); accv.w = fmaf(w2, h2.w, accv.w);
        accv.x = fmaf(w3, h3.x, accv.x); accv.y = fmaf(w3, h3.y, accv.y);
        accv.z = fmaf(w3, h3.z, accv.z); accv.w = fmaf(w3, h3.w, accv.w);
    }
    for (; t <= te; ++t) {
        float  wt = __ldg(prow + t);
        float4 hv = __ldg(h4 + (size_t)t * HS);
        accv.x = fmaf(wt, hv.x, accv.x);
        accv.y = fmaf(wt, hv.y, accv.y);
        accv.z = fmaf(wt, hv.z, accv.z);
        accv.w = fmaf(wt, hv.w, accv.w);
    }
    *out4 = accv;
}

// ---------------------------------------------------------------------------
extern "C" void kernel_launch(void* const* d_in, const int* in_sizes, int n_in,
                              void* d_out, int out_size)
{
    const float* hidden = (const float*)d_in[0];
    const float* alphas = (const float*)d_in[1];
    const int*   tlen   = (const int*)d_in[2];
    float* out = (float*)d_out;

    cif_scan_kernel<<<CIF_B, 256>>>(alphas, tlen);
    dim3 grid(CIF_L, CIF_B);
    cif_gather_kernel<<<grid, 128>>>(hidden, out);
}